// round 14
// baseline (speedup 1.0000x reference)
#include <cuda_runtime.h>
#include <cstdint>

// Problem shape (fixed): B=2, S=2048, D=1024, H=2048, E=8, k=2
#define T_TOK 4096   // B*S tokens
#define DIM   1024   // D
#define HID   2048   // H
#define NEXP  8      // E

// ---------------- static device scratch (no runtime allocation) -------------
__device__ int   g_cnt[NEXP];                       // tokens per expert
__device__ int   g_tok[NEXP * T_TOK];               // token*2 + slot
__device__ float g_score[NEXP * T_TOK];             // softmax score of that slot
__device__ float g_h[(size_t)NEXP * T_TOK * HID];   // hidden activations (per expert segment)
__device__ float g_eo[(size_t)T_TOK * 2 * DIM];     // per-(token,slot) expert output

// ---------------------------------------------------------------------------
__global__ void zero_cnt_kernel() {
    if (threadIdx.x < NEXP) g_cnt[threadIdx.x] = 0;
}

// One block (128 threads) per token: logits = x @ Wr + br, top-2, softmax,
// append to per-expert lists.
__global__ void router_kernel(const float* __restrict__ x,
                              const float* __restrict__ Wr,
                              const float* __restrict__ br) {
    const int t   = blockIdx.x;
    const int tid = threadIdx.x;

    float acc[NEXP];
#pragma unroll
    for (int e = 0; e < NEXP; e++) acc[e] = 0.f;

    const float4* Wr4 = reinterpret_cast<const float4*>(Wr);   // [D][E] rows of 8 floats
    const float*  xr  = x + (size_t)t * DIM;

#pragma unroll
    for (int it = 0; it < DIM / 128; it++) {
        int d = it * 128 + tid;
        float xv  = xr[d];
        float4 w0 = Wr4[d * 2];
        float4 w1 = Wr4[d * 2 + 1];
        acc[0] = fmaf(xv, w0.x, acc[0]); acc[1] = fmaf(xv, w0.y, acc[1]);
        acc[2] = fmaf(xv, w0.z, acc[2]); acc[3] = fmaf(xv, w0.w, acc[3]);
        acc[4] = fmaf(xv, w1.x, acc[4]); acc[5] = fmaf(xv, w1.y, acc[5]);
        acc[6] = fmaf(xv, w1.z, acc[6]); acc[7] = fmaf(xv, w1.w, acc[7]);
    }

    // warp reduce
#pragma unroll
    for (int o = 16; o > 0; o >>= 1) {
#pragma unroll
        for (int e = 0; e < NEXP; e++)
            acc[e] += __shfl_down_sync(0xffffffffu, acc[e], o);
    }

    __shared__ float sred[4][NEXP];
    const int wid  = tid >> 5;
    const int lane = tid & 31;
    if (lane == 0) {
#pragma unroll
        for (int e = 0; e < NEXP; e++) sred[wid][e] = acc[e];
    }
    __syncthreads();

    if (tid == 0) {
        float lg[NEXP];
#pragma unroll
        for (int e = 0; e < NEXP; e++)
            lg[e] = sred[0][e] + sred[1][e] + sred[2][e] + sred[3][e] + br[e];

        // top-2 (strict > keeps lowest index on ties, matching jax top_k)
        int i0 = 0;
#pragma unroll
        for (int e = 1; e < NEXP; e++) if (lg[e] > lg[i0]) i0 = e;
        int i1 = (i0 == 0) ? 1 : 0;
#pragma unroll
        for (int e = 0; e < NEXP; e++)
            if (e != i0 && lg[e] > lg[i1]) i1 = e;

        float ev  = expf(lg[i1] - lg[i0]);     // <= 1
        float inv = 1.f / (1.f + ev);
        float p0  = inv;
        float p1  = ev * inv;

        int pos0 = atomicAdd(&g_cnt[i0], 1);
        g_tok[i0 * T_TOK + pos0]   = t * 2;
        g_score[i0 * T_TOK + pos0] = p0;
        int pos1 = atomicAdd(&g_cnt[i1], 1);
        g_tok[i1 * T_TOK + pos1]   = t * 2 + 1;
        g_score[i1 * T_TOK + pos1] = p1;
    }
}

// ---------------------------------------------------------------------------
// GEMM1: for expert e, h[e*T + pos, :] = relu( x[tok(pos), :] @ W1[e] + b1[e] )
// Tile 128x128, BK=16, 256 threads, 8x8 micro-tile.
__global__ __launch_bounds__(256, 2)
void gemm1_kernel(const float* __restrict__ x,
                  const float* __restrict__ W1,
                  const float* __restrict__ b1) {
    const int e   = blockIdx.z;
    const int cnt = g_cnt[e];
    const int m0  = blockIdx.y * 128;
    if (m0 >= cnt) return;
    const int n0  = blockIdx.x * 128;

    __shared__ float  As[16][128];
    __shared__ float4 Bs[16][32];

    const int tid = threadIdx.x;
    const int tx  = tid & 15;
    const int ty  = tid >> 4;

    // A loading assignment: 512 float4 per K-tile, 2 per thread
    const int arow = tid >> 2;   // 0..63, second is +64
    const int akq  = tid & 3;    // float4 index along K within tile
    int tokA[2];
#pragma unroll
    for (int p = 0; p < 2; p++) {
        int pos = m0 + arow + p * 64;
        int tk  = 0;
        if (pos < cnt) tk = g_tok[e * T_TOK + pos] >> 1;   // token id
        tokA[p] = tk;
    }
    const float4* x4 = reinterpret_cast<const float4*>(x);

    // B loading assignment
    const int bn4 = tid & 31;
    const int bk  = tid >> 5;    // 0..7, +8 for p=1
    const float4* W4 = reinterpret_cast<const float4*>(W1);
    const size_t  wbase = (size_t)e * DIM * (HID / 4);

    float acc[8][8];
#pragma unroll
    for (int i = 0; i < 8; i++)
#pragma unroll
        for (int j = 0; j < 8; j++) acc[i][j] = 0.f;

    for (int k0 = 0; k0 < DIM; k0 += 16) {
#pragma unroll
        for (int p = 0; p < 2; p++) {
            float4 v = x4[(size_t)tokA[p] * (DIM / 4) + (k0 >> 2) + akq];
            int r = arow + p * 64;
            As[akq * 4 + 0][r] = v.x;
            As[akq * 4 + 1][r] = v.y;
            As[akq * 4 + 2][r] = v.z;
            As[akq * 4 + 3][r] = v.w;
        }
#pragma unroll
        for (int p = 0; p < 2; p++) {
            int k = k0 + bk + p * 8;
            Bs[bk + p * 8][bn4] = W4[wbase + (size_t)k * (HID / 4) + (n0 >> 2) + bn4];
        }
        __syncthreads();

#pragma unroll
        for (int kk = 0; kk < 16; kk++) {
            const float4* Ar = reinterpret_cast<const float4*>(&As[kk][0]);
            float4 a0 = Ar[ty * 2];
            float4 a1 = Ar[ty * 2 + 1];
            float4 b0 = Bs[kk][tx * 2];
            float4 b1v = Bs[kk][tx * 2 + 1];
            float av[8] = {a0.x, a0.y, a0.z, a0.w, a1.x, a1.y, a1.z, a1.w};
            float bv[8] = {b0.x, b0.y, b0.z, b0.w, b1v.x, b1v.y, b1v.z, b1v.w};
#pragma unroll
            for (int i = 0; i < 8; i++)
#pragma unroll
                for (int j = 0; j < 8; j++)
                    acc[i][j] = fmaf(av[i], bv[j], acc[i][j]);
        }
        __syncthreads();
    }

    // epilogue: + b1, relu, store to g_h
    const float4* b14 = reinterpret_cast<const float4*>(b1);
    float4 bb0 = b14[(e * HID + n0) / 4 + tx * 2];
    float4 bb1 = b14[(e * HID + n0) / 4 + tx * 2 + 1];
    float4* h4 = reinterpret_cast<float4*>(g_h);
#pragma unroll
    for (int i = 0; i < 8; i++) {
        int pos = m0 + ty * 8 + i;
        if (pos < cnt) {
            size_t base = ((size_t)e * T_TOK + pos) * (HID / 4) + (n0 >> 2) + tx * 2;
            float4 o0, o1;
            o0.x = fmaxf(acc[i][0] + bb0.x, 0.f);
            o0.y = fmaxf(acc[i][1] + bb0.y, 0.f);
            o0.z = fmaxf(acc[i][2] + bb0.z, 0.f);
            o0.w = fmaxf(acc[i][3] + bb0.w, 0.f);
            o1.x = fmaxf(acc[i][4] + bb1.x, 0.f);
            o1.y = fmaxf(acc[i][5] + bb1.y, 0.f);
            o1.z = fmaxf(acc[i][6] + bb1.z, 0.f);
            o1.w = fmaxf(acc[i][7] + bb1.w, 0.f);
            h4[base]     = o0;
            h4[base + 1] = o1;
        }
    }
}

// ---------------------------------------------------------------------------
// GEMM2: eo[tok2, :] = score * ( h[e*T+pos, :] @ W2[e] + b2[e] )
__global__ __launch_bounds__(256, 2)
void gemm2_kernel(const float* __restrict__ W2,
                  const float* __restrict__ b2) {
    const int e   = blockIdx.z;
    const int cnt = g_cnt[e];
    const int m0  = blockIdx.y * 128;
    if (m0 >= cnt) return;
    const int n0  = blockIdx.x * 128;   // over DIM

    __shared__ float  As[16][128];
    __shared__ float4 Bs[16][32];

    const int tid = threadIdx.x;
    const int tx  = tid & 15;
    const int ty  = tid >> 4;

    const int arow = tid >> 2;
    const int akq  = tid & 3;
    const int bn4  = tid & 31;
    const int bk   = tid >> 5;

    const float4* h4  = reinterpret_cast<const float4*>(g_h);
    const float4* W4  = reinterpret_cast<const float4*>(W2);
    const size_t  abase = ((size_t)e * T_TOK + m0) * (HID / 4);
    const size_t  wbase = (size_t)e * HID * (DIM / 4);

    float acc[8][8];
#pragma unroll
    for (int i = 0; i < 8; i++)
#pragma unroll
        for (int j = 0; j < 8; j++) acc[i][j] = 0.f;

    for (int k0 = 0; k0 < HID; k0 += 16) {
#pragma unroll
        for (int p = 0; p < 2; p++) {
            int r = arow + p * 64;
            // rows >= cnt read stale-but-finite scratch; stores are masked below
            float4 v = h4[abase + (size_t)r * (HID / 4) + (k0 >> 2) + akq];
            As[akq * 4 + 0][r] = v.x;
            As[akq * 4 + 1][r] = v.y;
            As[akq * 4 + 2][r] = v.z;
            As[akq * 4 + 3][r] = v.w;
        }
#pragma unroll
        for (int p = 0; p < 2; p++) {
            int k = k0 + bk + p * 8;
            Bs[bk + p * 8][bn4] = W4[wbase + (size_t)k * (DIM / 4) + (n0 >> 2) + bn4];
        }
        __syncthreads();

#pragma unroll
        for (int kk = 0; kk < 16; kk++) {
            const float4* Ar = reinterpret_cast<const float4*>(&As[kk][0]);
            float4 a0 = Ar[ty * 2];
            float4 a1 = Ar[ty * 2 + 1];
            float4 b0 = Bs[kk][tx * 2];
            float4 b1v = Bs[kk][tx * 2 + 1];
            float av[8] = {a0.x, a0.y, a0.z, a0.w, a1.x, a1.y, a1.z, a1.w};
            float bv[8] = {b0.x, b0.y, b0.z, b0.w, b1v.x, b1v.y, b1v.z, b1v.w};
#pragma unroll
            for (int i = 0; i < 8; i++)
#pragma unroll
                for (int j = 0; j < 8; j++)
                    acc[i][j] = fmaf(av[i], bv[j], acc[i][j]);
        }
        __syncthreads();
    }

    const float4* b24 = reinterpret_cast<const float4*>(b2);
    float4 bb0 = b24[(e * DIM + n0) / 4 + tx * 2];
    float4 bb1 = b24[(e * DIM + n0) / 4 + tx * 2 + 1];
    float4* eo4 = reinterpret_cast<float4*>(g_eo);
#pragma unroll
    for (int i = 0; i < 8; i++) {
        int pos = m0 + ty * 8 + i;
        if (pos < cnt) {
            int   entry = g_tok[e * T_TOK + pos];      // token*2 + slot
            float sc    = g_score[e * T_TOK + pos];
            size_t base = (size_t)entry * (DIM / 4) + (n0 >> 2) + tx * 2;
            float4 o0, o1;
            o0.x = (acc[i][0] + bb0.x) * sc;
            o0.y = (acc[i][1] + bb0.y) * sc;
            o0.z = (acc[i][2] + bb0.z) * sc;
            o0.w = (acc[i][3] + bb0.w) * sc;
            o1.x = (acc[i][4] + bb1.x) * sc;
            o1.y = (acc[i][5] + bb1.y) * sc;
            o1.z = (acc[i][6] + bb1.z) * sc;
            o1.w = (acc[i][7] + bb1.w) * sc;
            eo4[base]     = o0;
            eo4[base + 1] = o1;
        }
    }
}

// ---------------------------------------------------------------------------
// out[t, :] = eo[2t, :] + eo[2t+1, :]
__global__ void combine_kernel(float* __restrict__ out) {
    int i  = blockIdx.x * 256 + threadIdx.x;  // over T*D/4
    int t  = i >> 8;                          // D/4 = 256 float4 per row
    int d4 = i & 255;
    const float4* eo4 = reinterpret_cast<const float4*>(g_eo);
    float4 u = eo4[(size_t)(t * 2) * (DIM / 4) + d4];
    float4 v = eo4[(size_t)(t * 2 + 1) * (DIM / 4) + d4];
    float4 r;
    r.x = u.x + v.x; r.y = u.y + v.y; r.z = u.z + v.z; r.w = u.w + v.w;
    reinterpret_cast<float4*>(out)[i] = r;
}

// ---------------------------------------------------------------------------
extern "C" void kernel_launch(void* const* d_in, const int* in_sizes, int n_in,
                              void* d_out, int out_size) {
    (void)in_sizes; (void)n_in; (void)out_size;
    const float* x  = (const float*)d_in[0];
    const float* Wr = (const float*)d_in[1];
    const float* br = (const float*)d_in[2];
    const float* W1 = (const float*)d_in[3];
    const float* b1 = (const float*)d_in[4];
    const float* W2 = (const float*)d_in[5];
    const float* b2 = (const float*)d_in[6];
    // d_in[7] is k (==2), hardcoded

    zero_cnt_kernel<<<1, 32>>>();
    router_kernel<<<T_TOK, 128>>>(x, Wr, br);

    dim3 g1(HID / 128, T_TOK / 128, NEXP);   // early-exit past per-expert count
    gemm1_kernel<<<g1, 256>>>(x, W1, b1);

    dim3 g2(DIM / 128, T_TOK / 128, NEXP);
    gemm2_kernel<<<g2, 256>>>(W2, b2);

    combine_kernel<<<(T_TOK * DIM / 4) / 256, 256>>>((float*)d_out);
}

// round 16
// speedup vs baseline: 1.6037x; 1.6037x over previous
#include <cuda_runtime.h>
#include <cuda_bf16.h>
#include <cstdint>

// Problem shape (fixed): B=2, S=2048, D=1024, H=2048, E=8, k=2
#define T_TOK 4096
#define DIM   1024
#define HID   2048
#define NEXP  8

// ---------------- static device scratch (no runtime allocation) -------------
__device__ int   g_cnt[NEXP];
__device__ int   g_tok[NEXP * T_TOK];               // token*2 + slot
__device__ float g_score[NEXP * T_TOK];
__device__ float g_h[(size_t)NEXP * T_TOK * HID];   // hidden activations
__device__ float g_eo[(size_t)T_TOK * 2 * DIM];     // per-(token,slot) output
__device__ float g_w1t[(size_t)NEXP * HID * DIM];   // W1^T: [E][H][D]
__device__ float g_w2t[(size_t)NEXP * DIM * HID];   // W2^T: [E][D][H]

// ---------------------------------------------------------------------------
__global__ void zero_cnt_kernel() {
    if (threadIdx.x < NEXP) g_cnt[threadIdx.x] = 0;
}

__global__ void router_kernel(const float* __restrict__ x,
                              const float* __restrict__ Wr,
                              const float* __restrict__ br) {
    const int t   = blockIdx.x;
    const int tid = threadIdx.x;

    float acc[NEXP];
#pragma unroll
    for (int e = 0; e < NEXP; e++) acc[e] = 0.f;

    const float4* Wr4 = reinterpret_cast<const float4*>(Wr);
    const float*  xr  = x + (size_t)t * DIM;

#pragma unroll
    for (int it = 0; it < DIM / 128; it++) {
        int d = it * 128 + tid;
        float xv  = xr[d];
        float4 w0 = Wr4[d * 2];
        float4 w1 = Wr4[d * 2 + 1];
        acc[0] = fmaf(xv, w0.x, acc[0]); acc[1] = fmaf(xv, w0.y, acc[1]);
        acc[2] = fmaf(xv, w0.z, acc[2]); acc[3] = fmaf(xv, w0.w, acc[3]);
        acc[4] = fmaf(xv, w1.x, acc[4]); acc[5] = fmaf(xv, w1.y, acc[5]);
        acc[6] = fmaf(xv, w1.z, acc[6]); acc[7] = fmaf(xv, w1.w, acc[7]);
    }
#pragma unroll
    for (int o = 16; o > 0; o >>= 1) {
#pragma unroll
        for (int e = 0; e < NEXP; e++)
            acc[e] += __shfl_down_sync(0xffffffffu, acc[e], o);
    }
    __shared__ float sred[4][NEXP];
    const int wid  = tid >> 5;
    const int lane = tid & 31;
    if (lane == 0) {
#pragma unroll
        for (int e = 0; e < NEXP; e++) sred[wid][e] = acc[e];
    }
    __syncthreads();
    if (tid == 0) {
        float lg[NEXP];
#pragma unroll
        for (int e = 0; e < NEXP; e++)
            lg[e] = sred[0][e] + sred[1][e] + sred[2][e] + sred[3][e] + br[e];
        int i0 = 0;
#pragma unroll
        for (int e = 1; e < NEXP; e++) if (lg[e] > lg[i0]) i0 = e;
        int i1 = (i0 == 0) ? 1 : 0;
#pragma unroll
        for (int e = 0; e < NEXP; e++)
            if (e != i0 && lg[e] > lg[i1]) i1 = e;
        float ev  = expf(lg[i1] - lg[i0]);
        float inv = 1.f / (1.f + ev);
        int pos0 = atomicAdd(&g_cnt[i0], 1);
        g_tok[i0 * T_TOK + pos0]   = t * 2;
        g_score[i0 * T_TOK + pos0] = inv;
        int pos1 = atomicAdd(&g_cnt[i1], 1);
        g_tok[i1 * T_TOK + pos1]   = t * 2 + 1;
        g_score[i1 * T_TOK + pos1] = ev * inv;
    }
}

// ---------------- weight transposes (K-major B operands) ---------------------
__global__ void transpose_w1(const float* __restrict__ W1) {
    __shared__ float t[32][33];
    int e  = blockIdx.z;
    int c0 = blockIdx.x * 32;   // over H
    int r0 = blockIdx.y * 32;   // over D
    const float* s = W1 + (size_t)e * DIM * HID;
    float*       d = g_w1t + (size_t)e * HID * DIM;
    int x = threadIdx.x, y = threadIdx.y;
#pragma unroll
    for (int i = 0; i < 32; i += 8) t[y + i][x] = s[(size_t)(r0 + y + i) * HID + c0 + x];
    __syncthreads();
#pragma unroll
    for (int i = 0; i < 32; i += 8) d[(size_t)(c0 + y + i) * DIM + r0 + x] = t[x][y + i];
}

__global__ void transpose_w2(const float* __restrict__ W2) {
    __shared__ float t[32][33];
    int e  = blockIdx.z;
    int c0 = blockIdx.x * 32;   // over D
    int r0 = blockIdx.y * 32;   // over H
    const float* s = W2 + (size_t)e * HID * DIM;
    float*       d = g_w2t + (size_t)e * DIM * HID;
    int x = threadIdx.x, y = threadIdx.y;
#pragma unroll
    for (int i = 0; i < 32; i += 8) t[y + i][x] = s[(size_t)(r0 + y + i) * DIM + c0 + x];
    __syncthreads();
#pragma unroll
    for (int i = 0; i < 32; i += 8) d[(size_t)(c0 + y + i) * HID + r0 + x] = t[x][y + i];
}

// ---------------------------- mma.sync helpers -------------------------------
__device__ __forceinline__ void mma_bf16(float* c, const uint32_t* a, const uint32_t* b) {
    asm volatile(
        "mma.sync.aligned.m16n8k16.row.col.f32.bf16.bf16.f32 "
        "{%0,%1,%2,%3}, {%4,%5,%6,%7}, {%8,%9}, {%0,%1,%2,%3};"
        : "+f"(c[0]), "+f"(c[1]), "+f"(c[2]), "+f"(c[3])
        : "r"(a[0]), "r"(a[1]), "r"(a[2]), "r"(a[3]), "r"(b[0]), "r"(b[1]));
}

__device__ __forceinline__ void split2(float v0, float v1, uint32_t& h, uint32_t& l) {
    __nv_bfloat16 h0 = __float2bfloat16_rn(v0);
    __nv_bfloat16 h1 = __float2bfloat16_rn(v1);
    __nv_bfloat16 l0 = __float2bfloat16_rn(v0 - __bfloat162float(h0));
    __nv_bfloat16 l1 = __float2bfloat16_rn(v1 - __bfloat162float(h1));
    h = ((uint32_t)__bfloat16_as_ushort(h1) << 16) | (uint32_t)__bfloat16_as_ushort(h0);
    l = ((uint32_t)__bfloat16_as_ushort(l1) << 16) | (uint32_t)__bfloat16_as_ushort(l0);
}

// ---------------------------------------------------------------------------
// Grouped GEMM via mma.sync bf16 3-term split. 128x128 tile, BK=32, 256 thr.
// Warp layout: 2(m) x 4(n), warp tile 64x32, m16n8k16 fragments.
// smem: s_tok int[128] @0; bf16 planes @512: AH/AL/BH/BL, each [2][128][BKP=40]
#define BKP        40
#define PLANE      (128 * BKP)                 // elems per buf per plane
#define GEMM_SMEM  (512 + 8 * PLANE * 2)      // 512 + 81920 = 82432 B

template <int G2>
__global__ __launch_bounds__(256, 1)
void moe_gemm_mma(const float* __restrict__ x, const float* __restrict__ bias) {
    constexpr int KD     = G2 ? HID : DIM;
    constexpr int NSTEPS = KD / 32;

    const int e   = blockIdx.z;
    const int cnt = g_cnt[e];
    const int m0  = blockIdx.y * 128;
    if (m0 >= cnt) return;
    const int n0  = blockIdx.x * 128;

    extern __shared__ __align__(16) char smem[];
    int* s_tok = (int*)smem;
    __nv_bfloat16* sm = (__nv_bfloat16*)(smem + 512);
    // plane bases (element offsets): AH = buf*PLANE; AL = 2*PLANE + buf*PLANE; ...
    const int tid  = threadIdx.x;
    const int wid  = tid >> 5;
    const int lane = tid & 31;

    if (!G2) {
        if (tid < 128) {
            int pos = m0 + tid;
            s_tok[tid] = (pos < cnt) ? (g_tok[e * T_TOK + pos] >> 1) : 0;
        }
        __syncthreads();
    }

    // ---- loader mapping: thread covers (row = tid>>1, 16 k-floats) ----
    const int lrow = tid >> 1;
    const int koff = (tid & 1) * 16;
    const float* Abase = G2 ? (g_h + ((size_t)e * T_TOK + m0 + lrow) * HID)
                            : (x + (size_t)s_tok[lrow] * DIM);
    const float* Bbase = G2 ? (g_w2t + ((size_t)e * DIM + n0 + lrow) * HID)
                            : (g_w1t + ((size_t)e * HID + n0 + lrow) * DIM);

    // ---- warp tiling ----
    const int wm  = wid >> 2;     // 0..1
    const int wn  = wid & 3;      // 0..3
    const int g   = lane >> 2;    // group id 0..7
    const int tig = lane & 3;

    float c[4][4][4];
#pragma unroll
    for (int i = 0; i < 4; i++)
#pragma unroll
        for (int j = 0; j < 4; j++)
#pragma unroll
            for (int q = 0; q < 4; q++) c[i][j][q] = 0.f;

    float4 ra[4], rb[4];

    auto load_tile = [&](int s) {
        const float* ap = Abase + s * 32 + koff;
        const float* bp = Bbase + s * 32 + koff;
#pragma unroll
        for (int p = 0; p < 4; p++) {
            ra[p] = *reinterpret_cast<const float4*>(ap + p * 4);
            rb[p] = *reinterpret_cast<const float4*>(bp + p * 4);
        }
    };

    auto store_tile = [&](int buf) {
        uint32_t wh[8], wl[8];
#pragma unroll
        for (int p = 0; p < 4; p++) {
            split2(ra[p].x, ra[p].y, wh[p * 2],     wl[p * 2]);
            split2(ra[p].z, ra[p].w, wh[p * 2 + 1], wl[p * 2 + 1]);
        }
        int so = lrow * BKP + koff;
        *reinterpret_cast<uint4*>(&sm[buf * PLANE + so])             = make_uint4(wh[0], wh[1], wh[2], wh[3]);
        *reinterpret_cast<uint4*>(&sm[buf * PLANE + so + 8])         = make_uint4(wh[4], wh[5], wh[6], wh[7]);
        *reinterpret_cast<uint4*>(&sm[2 * PLANE + buf * PLANE + so])     = make_uint4(wl[0], wl[1], wl[2], wl[3]);
        *reinterpret_cast<uint4*>(&sm[2 * PLANE + buf * PLANE + so + 8]) = make_uint4(wl[4], wl[5], wl[6], wl[7]);
#pragma unroll
        for (int p = 0; p < 4; p++) {
            split2(rb[p].x, rb[p].y, wh[p * 2],     wl[p * 2]);
            split2(rb[p].z, rb[p].w, wh[p * 2 + 1], wl[p * 2 + 1]);
        }
        *reinterpret_cast<uint4*>(&sm[4 * PLANE + buf * PLANE + so])     = make_uint4(wh[0], wh[1], wh[2], wh[3]);
        *reinterpret_cast<uint4*>(&sm[4 * PLANE + buf * PLANE + so + 8]) = make_uint4(wh[4], wh[5], wh[6], wh[7]);
        *reinterpret_cast<uint4*>(&sm[6 * PLANE + buf * PLANE + so])     = make_uint4(wl[0], wl[1], wl[2], wl[3]);
        *reinterpret_cast<uint4*>(&sm[6 * PLANE + buf * PLANE + so + 8]) = make_uint4(wl[4], wl[5], wl[6], wl[7]);
    };

    auto compute = [&](int buf) {
        const __nv_bfloat16* pAH = sm + buf * PLANE;
        const __nv_bfloat16* pAL = sm + 2 * PLANE + buf * PLANE;
        const __nv_bfloat16* pBH = sm + 4 * PLANE + buf * PLANE;
        const __nv_bfloat16* pBL = sm + 6 * PLANE + buf * PLANE;
#pragma unroll
        for (int kk = 0; kk < 32; kk += 16) {
            uint32_t ah[4][4], al[4][4], bh[4][2], bl[4][2];
            const int cb = kk + 2 * tig;
#pragma unroll
            for (int i = 0; i < 4; i++) {
                int r = wm * 64 + i * 16 + g;
                ah[i][0] = *reinterpret_cast<const uint32_t*>(&pAH[r * BKP + cb]);
                ah[i][1] = *reinterpret_cast<const uint32_t*>(&pAH[(r + 8) * BKP + cb]);
                ah[i][2] = *reinterpret_cast<const uint32_t*>(&pAH[r * BKP + cb + 8]);
                ah[i][3] = *reinterpret_cast<const uint32_t*>(&pAH[(r + 8) * BKP + cb + 8]);
                al[i][0] = *reinterpret_cast<const uint32_t*>(&pAL[r * BKP + cb]);
                al[i][1] = *reinterpret_cast<const uint32_t*>(&pAL[(r + 8) * BKP + cb]);
                al[i][2] = *reinterpret_cast<const uint32_t*>(&pAL[r * BKP + cb + 8]);
                al[i][3] = *reinterpret_cast<const uint32_t*>(&pAL[(r + 8) * BKP + cb + 8]);
            }
#pragma unroll
            for (int j = 0; j < 4; j++) {
                int n = wn * 32 + j * 8 + g;
                bh[j][0] = *reinterpret_cast<const uint32_t*>(&pBH[n * BKP + cb]);
                bh[j][1] = *reinterpret_cast<const uint32_t*>(&pBH[n * BKP + cb + 8]);
                bl[j][0] = *reinterpret_cast<const uint32_t*>(&pBL[n * BKP + cb]);
                bl[j][1] = *reinterpret_cast<const uint32_t*>(&pBL[n * BKP + cb + 8]);
            }
#pragma unroll
            for (int i = 0; i < 4; i++)
#pragma unroll
                for (int j = 0; j < 4; j++) {
                    mma_bf16(c[i][j], ah[i], bh[j]);
                    mma_bf16(c[i][j], ah[i], bl[j]);
                    mma_bf16(c[i][j], al[i], bh[j]);
                }
        }
    };

    // ---- pipelined main loop ----
    load_tile(0);
    store_tile(0);
    __syncthreads();
    for (int s = 0; s < NSTEPS; s++) {
        if (s + 1 < NSTEPS) load_tile(s + 1);
        compute(s & 1);
        if (s + 1 < NSTEPS) store_tile((s + 1) & 1);
        __syncthreads();
    }

    // ---- epilogue ----
    if (!G2) {
#pragma unroll
        for (int j = 0; j < 4; j++) {
            int col = n0 + wn * 32 + j * 8 + 2 * tig;
            float2 bv = *reinterpret_cast<const float2*>(&bias[e * HID + col]);
#pragma unroll
            for (int i = 0; i < 4; i++) {
                int pos0 = m0 + wm * 64 + i * 16 + g;
                int pos1 = pos0 + 8;
                if (pos0 < cnt) {
                    float2 o;
                    o.x = fmaxf(c[i][j][0] + bv.x, 0.f);
                    o.y = fmaxf(c[i][j][1] + bv.y, 0.f);
                    *reinterpret_cast<float2*>(&g_h[((size_t)e * T_TOK + pos0) * HID + col]) = o;
                }
                if (pos1 < cnt) {
                    float2 o;
                    o.x = fmaxf(c[i][j][2] + bv.x, 0.f);
                    o.y = fmaxf(c[i][j][3] + bv.y, 0.f);
                    *reinterpret_cast<float2*>(&g_h[((size_t)e * T_TOK + pos1) * HID + col]) = o;
                }
            }
        }
    } else {
#pragma unroll
        for (int i = 0; i < 4; i++) {
            int pos0 = m0 + wm * 64 + i * 16 + g;
            int pos1 = pos0 + 8;
            int   en0 = 0, en1 = 0;
            float sc0 = 0.f, sc1 = 0.f;
            if (pos0 < cnt) { en0 = g_tok[e * T_TOK + pos0]; sc0 = g_score[e * T_TOK + pos0]; }
            if (pos1 < cnt) { en1 = g_tok[e * T_TOK + pos1]; sc1 = g_score[e * T_TOK + pos1]; }
#pragma unroll
            for (int j = 0; j < 4; j++) {
                int col = n0 + wn * 32 + j * 8 + 2 * tig;
                float2 bv = *reinterpret_cast<const float2*>(&bias[e * DIM + col]);
                if (pos0 < cnt) {
                    float2 o;
                    o.x = (c[i][j][0] + bv.x) * sc0;
                    o.y = (c[i][j][1] + bv.y) * sc0;
                    *reinterpret_cast<float2*>(&g_eo[(size_t)en0 * DIM + col]) = o;
                }
                if (pos1 < cnt) {
                    float2 o;
                    o.x = (c[i][j][2] + bv.x) * sc1;
                    o.y = (c[i][j][3] + bv.y) * sc1;
                    *reinterpret_cast<float2*>(&g_eo[(size_t)en1 * DIM + col]) = o;
                }
            }
        }
    }
}

// ---------------------------------------------------------------------------
__global__ void combine_kernel(float* __restrict__ out) {
    int i  = blockIdx.x * 256 + threadIdx.x;
    int t  = i >> 8;
    int d4 = i & 255;
    const float4* eo4 = reinterpret_cast<const float4*>(g_eo);
    float4 u = eo4[(size_t)(t * 2) * (DIM / 4) + d4];
    float4 v = eo4[(size_t)(t * 2 + 1) * (DIM / 4) + d4];
    float4 r;
    r.x = u.x + v.x; r.y = u.y + v.y; r.z = u.z + v.z; r.w = u.w + v.w;
    reinterpret_cast<float4*>(out)[i] = r;
}

// ---------------------------------------------------------------------------
extern "C" void kernel_launch(void* const* d_in, const int* in_sizes, int n_in,
                              void* d_out, int out_size) {
    (void)in_sizes; (void)n_in; (void)out_size;
    const float* x  = (const float*)d_in[0];
    const float* Wr = (const float*)d_in[1];
    const float* br = (const float*)d_in[2];
    const float* W1 = (const float*)d_in[3];
    const float* b1 = (const float*)d_in[4];
    const float* W2 = (const float*)d_in[5];
    const float* b2 = (const float*)d_in[6];

    cudaFuncSetAttribute(moe_gemm_mma<0>,
                         cudaFuncAttributeMaxDynamicSharedMemorySize, GEMM_SMEM);
    cudaFuncSetAttribute(moe_gemm_mma<1>,
                         cudaFuncAttributeMaxDynamicSharedMemorySize, GEMM_SMEM);

    zero_cnt_kernel<<<1, 32>>>();
    router_kernel<<<T_TOK, 128>>>(x, Wr, br);

    transpose_w1<<<dim3(HID / 32, DIM / 32, NEXP), dim3(32, 8)>>>(W1);
    transpose_w2<<<dim3(DIM / 32, HID / 32, NEXP), dim3(32, 8)>>>(W2);

    dim3 g1(HID / 128, T_TOK / 128, NEXP);
    moe_gemm_mma<0><<<g1, 256, GEMM_SMEM>>>(x, b1);

    dim3 g2(DIM / 128, T_TOK / 128, NEXP);
    moe_gemm_mma<1><<<g2, 256, GEMM_SMEM>>>(x, b2);

    combine_kernel<<<(T_TOK * DIM / 4) / 256, 256>>>((float*)d_out);
}

// round 17
// speedup vs baseline: 2.3252x; 1.4499x over previous
#include <cuda_runtime.h>
#include <cuda_bf16.h>
#include <cstdint>

// Problem shape (fixed): B=2, S=2048, D=1024, H=2048, E=8, k=2
#define T_TOK 4096
#define DIM   1024
#define HID   2048
#define NEXP  8

// ---------------- static device scratch (no runtime allocation) -------------
__device__ int   g_cnt[NEXP];
__device__ int   g_tok[NEXP * T_TOK];               // token*2 + slot
__device__ float g_score[NEXP * T_TOK];
__device__ float g_eo[(size_t)T_TOK * 2 * DIM];     // per-(token,slot) output

// bf16 hi/lo split planes
__device__ __nv_bfloat16 g_xh[(size_t)T_TOK * DIM];
__device__ __nv_bfloat16 g_xl[(size_t)T_TOK * DIM];
__device__ __nv_bfloat16 g_hh[(size_t)NEXP * T_TOK * HID];
__device__ __nv_bfloat16 g_hl[(size_t)NEXP * T_TOK * HID];
__device__ __nv_bfloat16 g_w1h[(size_t)NEXP * HID * DIM];  // W1^T hi  [E][H][D]
__device__ __nv_bfloat16 g_w1l[(size_t)NEXP * HID * DIM];
__device__ __nv_bfloat16 g_w2h[(size_t)NEXP * DIM * HID];  // W2^T hi  [E][D][H]
__device__ __nv_bfloat16 g_w2l[(size_t)NEXP * DIM * HID];

// ---------------------------------------------------------------------------
__device__ __forceinline__ uint32_t smem_u32(const void* p) {
    uint32_t a;
    asm("{ .reg .u64 t; cvta.to.shared.u64 t, %1; cvt.u32.u64 %0, t; }"
        : "=r"(a) : "l"(p));
    return a;
}
__device__ __forceinline__ void split1(float v, __nv_bfloat16& h, __nv_bfloat16& l) {
    h = __float2bfloat16_rn(v);
    l = __float2bfloat16_rn(v - __bfloat162float(h));
}
__device__ __forceinline__ uint32_t pack2(__nv_bfloat16 a, __nv_bfloat16 b) {
    return ((uint32_t)__bfloat16_as_ushort(b) << 16) | (uint32_t)__bfloat16_as_ushort(a);
}

#define CP16(dst, src) \
    asm volatile("cp.async.cg.shared.global [%0], [%1], 16;" :: "r"(dst), "l"(src))
#define CP_COMMIT() asm volatile("cp.async.commit_group;" ::: "memory")
#define CP_WAIT1()  asm volatile("cp.async.wait_group 1;" ::: "memory")

#define LDSM4(r, a) \
    asm volatile("ldmatrix.sync.aligned.m8n8.x4.shared.b16 {%0,%1,%2,%3}, [%4];" \
                 : "=r"((r)[0]), "=r"((r)[1]), "=r"((r)[2]), "=r"((r)[3]) : "r"(a))

__device__ __forceinline__ void mma_bf16(float* c, const uint32_t* a, const uint32_t* b) {
    asm volatile(
        "mma.sync.aligned.m16n8k16.row.col.f32.bf16.bf16.f32 "
        "{%0,%1,%2,%3}, {%4,%5,%6,%7}, {%8,%9}, {%0,%1,%2,%3};"
        : "+f"(c[0]), "+f"(c[1]), "+f"(c[2]), "+f"(c[3])
        : "r"(a[0]), "r"(a[1]), "r"(a[2]), "r"(a[3]), "r"(b[0]), "r"(b[1]));
}

// ---------------------------------------------------------------------------
__global__ void zero_cnt_kernel() {
    if (threadIdx.x < NEXP) g_cnt[threadIdx.x] = 0;
}

// router + x-split fused would complicate; keep router as-is
__global__ void router_kernel(const float* __restrict__ x,
                              const float* __restrict__ Wr,
                              const float* __restrict__ br) {
    const int t   = blockIdx.x;
    const int tid = threadIdx.x;

    float acc[NEXP];
#pragma unroll
    for (int e = 0; e < NEXP; e++) acc[e] = 0.f;

    const float4* Wr4 = reinterpret_cast<const float4*>(Wr);
    const float*  xr  = x + (size_t)t * DIM;

#pragma unroll
    for (int it = 0; it < DIM / 128; it++) {
        int d = it * 128 + tid;
        float xv  = xr[d];
        float4 w0 = Wr4[d * 2];
        float4 w1 = Wr4[d * 2 + 1];
        acc[0] = fmaf(xv, w0.x, acc[0]); acc[1] = fmaf(xv, w0.y, acc[1]);
        acc[2] = fmaf(xv, w0.z, acc[2]); acc[3] = fmaf(xv, w0.w, acc[3]);
        acc[4] = fmaf(xv, w1.x, acc[4]); acc[5] = fmaf(xv, w1.y, acc[5]);
        acc[6] = fmaf(xv, w1.z, acc[6]); acc[7] = fmaf(xv, w1.w, acc[7]);
    }
#pragma unroll
    for (int o = 16; o > 0; o >>= 1) {
#pragma unroll
        for (int e = 0; e < NEXP; e++)
            acc[e] += __shfl_down_sync(0xffffffffu, acc[e], o);
    }
    __shared__ float sred[4][NEXP];
    const int wid  = tid >> 5;
    const int lane = tid & 31;
    if (lane == 0) {
#pragma unroll
        for (int e = 0; e < NEXP; e++) sred[wid][e] = acc[e];
    }
    __syncthreads();
    if (tid == 0) {
        float lg[NEXP];
#pragma unroll
        for (int e = 0; e < NEXP; e++)
            lg[e] = sred[0][e] + sred[1][e] + sred[2][e] + sred[3][e] + br[e];
        int i0 = 0;
#pragma unroll
        for (int e = 1; e < NEXP; e++) if (lg[e] > lg[i0]) i0 = e;
        int i1 = (i0 == 0) ? 1 : 0;
#pragma unroll
        for (int e = 0; e < NEXP; e++)
            if (e != i0 && lg[e] > lg[i1]) i1 = e;
        float ev  = expf(lg[i1] - lg[i0]);
        float inv = 1.f / (1.f + ev);
        int pos0 = atomicAdd(&g_cnt[i0], 1);
        g_tok[i0 * T_TOK + pos0]   = t * 2;
        g_score[i0 * T_TOK + pos0] = inv;
        int pos1 = atomicAdd(&g_cnt[i1], 1);
        g_tok[i1 * T_TOK + pos1]   = t * 2 + 1;
        g_score[i1 * T_TOK + pos1] = ev * inv;
    }
}

// split x into bf16 hi/lo planes
__global__ void split_x_kernel(const float* __restrict__ x) {
    int i = blockIdx.x * 256 + threadIdx.x;          // over T*D/4
    float4 v = reinterpret_cast<const float4*>(x)[i];
    __nv_bfloat16 h0, h1, h2, h3, l0, l1, l2, l3;
    split1(v.x, h0, l0); split1(v.y, h1, l1);
    split1(v.z, h2, l2); split1(v.w, h3, l3);
    uint2 hh = make_uint2(pack2(h0, h1), pack2(h2, h3));
    uint2 ll = make_uint2(pack2(l0, l1), pack2(l2, l3));
    reinterpret_cast<uint2*>(g_xh)[i] = hh;
    reinterpret_cast<uint2*>(g_xl)[i] = ll;
}

// ---------------- weight transposes + split (once per launch) ----------------
__global__ void transpose_w1(const float* __restrict__ W1) {
    __shared__ float t[32][33];
    int e  = blockIdx.z;
    int c0 = blockIdx.x * 32;   // over H
    int r0 = blockIdx.y * 32;   // over D
    const float* s = W1 + (size_t)e * DIM * HID;
    size_t dbase = (size_t)e * HID * DIM;
    int x = threadIdx.x, y = threadIdx.y;
#pragma unroll
    for (int i = 0; i < 32; i += 8) t[y + i][x] = s[(size_t)(r0 + y + i) * HID + c0 + x];
    __syncthreads();
#pragma unroll
    for (int i = 0; i < 32; i += 8) {
        float v = t[x][y + i];
        __nv_bfloat16 h, l; split1(v, h, l);
        size_t idx = dbase + (size_t)(c0 + y + i) * DIM + r0 + x;
        g_w1h[idx] = h; g_w1l[idx] = l;
    }
}

__global__ void transpose_w2(const float* __restrict__ W2) {
    __shared__ float t[32][33];
    int e  = blockIdx.z;
    int c0 = blockIdx.x * 32;   // over D
    int r0 = blockIdx.y * 32;   // over H
    const float* s = W2 + (size_t)e * HID * DIM;
    size_t dbase = (size_t)e * DIM * HID;
    int x = threadIdx.x, y = threadIdx.y;
#pragma unroll
    for (int i = 0; i < 32; i += 8) t[y + i][x] = s[(size_t)(r0 + y + i) * DIM + c0 + x];
    __syncthreads();
#pragma unroll
    for (int i = 0; i < 32; i += 8) {
        float v = t[x][y + i];
        __nv_bfloat16 h, l; split1(v, h, l);
        size_t idx = dbase + (size_t)(c0 + y + i) * HID + r0 + x;
        g_w2h[idx] = h; g_w2l[idx] = l;
    }
}

// ---------------------------------------------------------------------------
// Grouped GEMM: cp.async 3-stage + ldmatrix + bf16 3-term mma.sync.
// 128x128 tile, BK=32, 256 threads, warps 2(m)x4(n), warp tile 64x32.
// smem buffer (per stage): 4 planes (AH, AL, BH, BL), each 128 rows x 80B
//   (padded: 32 bf16 data + 8 pad) = 10240 B; stage = 40960 B; 3 stages.
#define ROWB   80
#define PLANEB 10240
#define STAGEB 40960
#define TOKOFF (3 * STAGEB)
#define GEMM_SMEM (TOKOFF + 512)

template <int G2>
__global__ __launch_bounds__(256, 1)
void moe_gemm_mma(const float* __restrict__ bias) {
    constexpr int KD     = G2 ? HID : DIM;
    constexpr int NSTEPS = KD / 32;

    const int e   = blockIdx.z;
    const int cnt = g_cnt[e];
    const int m0  = blockIdx.y * 128;
    if (m0 >= cnt) return;
    const int n0  = blockIdx.x * 128;

    extern __shared__ __align__(16) char smem[];
    const uint32_t sb  = smem_u32(smem);
    int* s_tok = (int*)(smem + TOKOFF);
    const int tid  = threadIdx.x;
    const int wid  = tid >> 5;
    const int lane = tid & 31;

    if (!G2) {
        if (tid < 128) {
            int pos = m0 + tid;
            s_tok[tid] = (pos < cnt) ? (g_tok[e * T_TOK + pos] >> 1) : 0;
        }
        __syncthreads();
    }

    // ---- cp.async copy assignments: 2048 x 16B chunks per stage, 8/thread ----
    const char* src[8];
    uint32_t    dst[8];
#pragma unroll
    for (int t = 0; t < 8; t++) {
        int c   = tid + t * 256;
        int p   = c >> 9;          // plane 0..3
        int w   = c & 511;
        int row = w >> 2;
        int q   = w & 3;
        const __nv_bfloat16* gp;
        if (p == 0)      gp = G2 ? g_hh + ((size_t)e * T_TOK + m0 + row) * HID
                                 : g_xh + (size_t)s_tok[row] * DIM;
        else if (p == 1) gp = G2 ? g_hl + ((size_t)e * T_TOK + m0 + row) * HID
                                 : g_xl + (size_t)s_tok[row] * DIM;
        else if (p == 2) gp = G2 ? g_w2h + ((size_t)e * DIM + n0 + row) * HID
                                 : g_w1h + ((size_t)e * HID + n0 + row) * DIM;
        else             gp = G2 ? g_w2l + ((size_t)e * DIM + n0 + row) * HID
                                 : g_w1l + ((size_t)e * HID + n0 + row) * DIM;
        src[t] = (const char*)(gp + q * 8);
        dst[t] = sb + p * PLANEB + row * ROWB + q * 16;
    }

    auto issue = [&](int stage, int s) {
        uint32_t so = stage * STAGEB;
        size_t   go = (size_t)s * 64;
#pragma unroll
        for (int t = 0; t < 8; t++) CP16(dst[t] + so, src[t] + go);
    };

    // ---- ldmatrix lane addresses ----
    const int wm = wid >> 2;   // 0..1
    const int wn = wid & 3;    // 0..3
    uint32_t laneA[4], laneB[2];
#pragma unroll
    for (int i = 0; i < 4; i++)
        laneA[i] = (uint32_t)((wm * 64 + i * 16 + (lane & 15)) * ROWB + (lane >> 4) * 16);
#pragma unroll
    for (int jj = 0; jj < 2; jj++)
        laneB[jj] = (uint32_t)(2 * PLANEB +
                    (wn * 32 + jj * 16 + (lane >> 4) * 8 + (lane & 7)) * ROWB +
                    ((lane >> 3) & 1) * 16);

    float c[4][4][4];
#pragma unroll
    for (int i = 0; i < 4; i++)
#pragma unroll
        for (int j = 0; j < 4; j++)
#pragma unroll
            for (int q = 0; q < 4; q++) c[i][j][q] = 0.f;

    auto compute = [&](int buf) {
        const uint32_t base = sb + buf * STAGEB;
#pragma unroll
        for (int kh = 0; kh < 2; kh++) {
            const uint32_t kb = kh * 32;   // byte offset for 16-element k half
            uint32_t ah[4][4], al[4][4], bh[2][4], bl[2][4];
#pragma unroll
            for (int i = 0; i < 4; i++) {
                LDSM4(ah[i], base + laneA[i] + kb);
                LDSM4(al[i], base + PLANEB + laneA[i] + kb);
            }
#pragma unroll
            for (int jj = 0; jj < 2; jj++) {
                LDSM4(bh[jj], base + laneB[jj] + kb);
                LDSM4(bl[jj], base + PLANEB + laneB[jj] + kb);
            }
#pragma unroll
            for (int i = 0; i < 4; i++)
#pragma unroll
                for (int j = 0; j < 4; j++) {
                    const uint32_t* bhp = &bh[j >> 1][(j & 1) * 2];
                    const uint32_t* blp = &bl[j >> 1][(j & 1) * 2];
                    mma_bf16(c[i][j], ah[i], bhp);
                    mma_bf16(c[i][j], ah[i], blp);
                    mma_bf16(c[i][j], al[i], bhp);
                }
        }
    };

    // ---- 3-stage pipeline ----
    issue(0, 0); CP_COMMIT();
    issue(1, 1); CP_COMMIT();
    for (int s = 0; s < NSTEPS; s++) {
        CP_WAIT1();
        __syncthreads();
        compute(s % 3);
        int nx = s + 2;
        if (nx < NSTEPS) issue(nx % 3, nx);
        CP_COMMIT();
    }

    // ---- epilogue ----
    const int g   = lane >> 2;
    const int tig = lane & 3;
    if (!G2) {
#pragma unroll
        for (int j = 0; j < 4; j++) {
            int col = n0 + wn * 32 + j * 8 + 2 * tig;
            float2 bv = *reinterpret_cast<const float2*>(&bias[e * HID + col]);
#pragma unroll
            for (int i = 0; i < 4; i++) {
                int pos0 = m0 + wm * 64 + i * 16 + g;
                int pos1 = pos0 + 8;
                if (pos0 < cnt) {
                    float v0 = fmaxf(c[i][j][0] + bv.x, 0.f);
                    float v1 = fmaxf(c[i][j][1] + bv.y, 0.f);
                    __nv_bfloat16 h0, l0, h1, l1;
                    split1(v0, h0, l0); split1(v1, h1, l1);
                    size_t idx = ((size_t)e * T_TOK + pos0) * HID + col;
                    *reinterpret_cast<uint32_t*>(&g_hh[idx]) = pack2(h0, h1);
                    *reinterpret_cast<uint32_t*>(&g_hl[idx]) = pack2(l0, l1);
                }
                if (pos1 < cnt) {
                    float v0 = fmaxf(c[i][j][2] + bv.x, 0.f);
                    float v1 = fmaxf(c[i][j][3] + bv.y, 0.f);
                    __nv_bfloat16 h0, l0, h1, l1;
                    split1(v0, h0, l0); split1(v1, h1, l1);
                    size_t idx = ((size_t)e * T_TOK + pos1) * HID + col;
                    *reinterpret_cast<uint32_t*>(&g_hh[idx]) = pack2(h0, h1);
                    *reinterpret_cast<uint32_t*>(&g_hl[idx]) = pack2(l0, l1);
                }
            }
        }
    } else {
#pragma unroll
        for (int i = 0; i < 4; i++) {
            int pos0 = m0 + wm * 64 + i * 16 + g;
            int pos1 = pos0 + 8;
            int   en0 = 0, en1 = 0;
            float sc0 = 0.f, sc1 = 0.f;
            if (pos0 < cnt) { en0 = g_tok[e * T_TOK + pos0]; sc0 = g_score[e * T_TOK + pos0]; }
            if (pos1 < cnt) { en1 = g_tok[e * T_TOK + pos1]; sc1 = g_score[e * T_TOK + pos1]; }
#pragma unroll
            for (int j = 0; j < 4; j++) {
                int col = n0 + wn * 32 + j * 8 + 2 * tig;
                float2 bv = *reinterpret_cast<const float2*>(&bias[e * DIM + col]);
                if (pos0 < cnt) {
                    float2 o;
                    o.x = (c[i][j][0] + bv.x) * sc0;
                    o.y = (c[i][j][1] + bv.y) * sc0;
                    *reinterpret_cast<float2*>(&g_eo[(size_t)en0 * DIM + col]) = o;
                }
                if (pos1 < cnt) {
                    float2 o;
                    o.x = (c[i][j][2] + bv.x) * sc1;
                    o.y = (c[i][j][3] + bv.y) * sc1;
                    *reinterpret_cast<float2*>(&g_eo[(size_t)en1 * DIM + col]) = o;
                }
            }
        }
    }
}

// ---------------------------------------------------------------------------
__global__ void combine_kernel(float* __restrict__ out) {
    int i  = blockIdx.x * 256 + threadIdx.x;
    int t  = i >> 8;
    int d4 = i & 255;
    const float4* eo4 = reinterpret_cast<const float4*>(g_eo);
    float4 u = eo4[(size_t)(t * 2) * (DIM / 4) + d4];
    float4 v = eo4[(size_t)(t * 2 + 1) * (DIM / 4) + d4];
    float4 r;
    r.x = u.x + v.x; r.y = u.y + v.y; r.z = u.z + v.z; r.w = u.w + v.w;
    reinterpret_cast<float4*>(out)[i] = r;
}

// ---------------------------------------------------------------------------
extern "C" void kernel_launch(void* const* d_in, const int* in_sizes, int n_in,
                              void* d_out, int out_size) {
    (void)in_sizes; (void)n_in; (void)out_size;
    const float* x  = (const float*)d_in[0];
    const float* Wr = (const float*)d_in[1];
    const float* br = (const float*)d_in[2];
    const float* W1 = (const float*)d_in[3];
    const float* b1 = (const float*)d_in[4];
    const float* W2 = (const float*)d_in[5];
    const float* b2 = (const float*)d_in[6];

    cudaFuncSetAttribute(moe_gemm_mma<0>,
                         cudaFuncAttributeMaxDynamicSharedMemorySize, GEMM_SMEM);
    cudaFuncSetAttribute(moe_gemm_mma<1>,
                         cudaFuncAttributeMaxDynamicSharedMemorySize, GEMM_SMEM);

    zero_cnt_kernel<<<1, 32>>>();
    router_kernel<<<T_TOK, 128>>>(x, Wr, br);
    split_x_kernel<<<(T_TOK * DIM / 4) / 256, 256>>>(x);

    transpose_w1<<<dim3(HID / 32, DIM / 32, NEXP), dim3(32, 8)>>>(W1);
    transpose_w2<<<dim3(DIM / 32, HID / 32, NEXP), dim3(32, 8)>>>(W2);

    dim3 g1(HID / 128, T_TOK / 128, NEXP);
    moe_gemm_mma<0><<<g1, 256, GEMM_SMEM>>>(b1);

    dim3 g2(DIM / 128, T_TOK / 128, NEXP);
    moe_gemm_mma<1><<<g2, 256, GEMM_SMEM>>>(b2);

    combine_kernel<<<(T_TOK * DIM / 4) / 256, 256>>>((float*)d_out);
}